// round 15
// baseline (speedup 1.0000x reference)
#include <cuda_runtime.h>

typedef unsigned long long u64;

// ---------------- packed f32x2 helpers (sm_103a) ----------------
__device__ __forceinline__ u64 pk2(float lo, float hi) {
    u64 r;
    asm("mov.b64 %0, {%1, %2};" : "=l"(r) : "f"(lo), "f"(hi));
    return r;
}
__device__ __forceinline__ void unpk2(u64 v, float& lo, float& hi) {
    asm("mov.b64 {%0, %1}, %2;" : "=f"(lo), "=f"(hi) : "l"(v));
}
__device__ __forceinline__ u64 mul2(u64 a, u64 b) {
    u64 r;
    asm("mul.rn.f32x2 %0, %1, %2;" : "=l"(r) : "l"(a), "l"(b));
    return r;
}
__device__ __forceinline__ u64 fma2(u64 a, u64 b, u64 c) {
    u64 r;
    asm("fma.rn.f32x2 %0, %1, %2, %3;" : "=l"(r) : "l"(a), "l"(b), "l"(c));
    return r;
}

// Flat constant layout (40 x u64, both f32x2 lanes duplicated).
#define IK0 0    // 6: F0 monomial coeffs
#define IK1 6    // 5: F1
#define IK2 11   // 6: F2
#define IK3 17   // 13: F3
#define IW0 30   // 4: head row 0
#define IW1 34   // 4: head row 1
#define IB0 38
#define IB1 39
#define NCONST 40

__device__ u64 g_scratch[NCONST];
__constant__ u64 c_flat[NCONST];

__global__ void setup_kernel(const float* __restrict__ weights,
                             const float* __restrict__ W,
                             const float* __restrict__ b) {
    __shared__ float G[4][81];
    int tid = threadIdx.x;

    // --- 1. simulate circuit features on the 3^4 grid x_i in {0, pi/2, pi} ---
    if (tid < 81) {
        const float HP = 1.57079632679489662f;  // pi/2
        int d0 = tid / 27, d1 = (tid / 9) % 3, d2 = (tid / 3) % 3, d3 = tid % 3;
        float xg[4] = { d0 * HP, d1 * HP, d2 * HP, d3 * HP };
        float cc[4], ss[4];
        for (int i = 0; i < 4; ++i) {
            float h = 0.5f * xg[i];
            cc[i] = cosf(h);
            ss[i] = sinf(h);
        }
        float st[16];
        for (int s = 0; s < 16; ++s) {
            float v = 1.0f;
            for (int i = 0; i < 4; ++i) v *= ((s >> (3 - i)) & 1) ? ss[i] : cc[i];
            st[s] = v;
        }
        for (int l = 0; l < 2; ++l) {
            for (int i = 0; i < 4; ++i) {               // CNOT ring
                int c = i, tq = (i + 1) & 3;
                int mc = 1 << (3 - c), mt = 1 << (3 - tq);
                for (int s = 0; s < 16; ++s)
                    if ((s & mc) && !(s & mt)) {
                        float tmp = st[s]; st[s] = st[s | mt]; st[s | mt] = tmp;
                    }
            }
            for (int i = 0; i < 4; ++i) {               // RY(weights[l][i])
                float h = 0.5f * weights[l * 4 + i];
                float c = cosf(h), sn = sinf(h);
                int m = 1 << (3 - i);
                for (int s = 0; s < 16; ++s)
                    if (!(s & m)) {
                        float a0 = st[s], a1 = st[s | m];
                        st[s]     = c * a0 - sn * a1;
                        st[s | m] = sn * a0 + c * a1;
                    }
            }
        }
        for (int q = 0; q < 4; ++q) {
            int m = 1 << (3 - q);
            float f = 0.0f;
            for (int s = 0; s < 16; ++s) {
                float p = st[s] * st[s];
                f += (s & m) ? -p : p;
            }
            G[q][tid] = f;
        }
    }
    __syncthreads();

    // --- 2. exact per-axis inverse transform: values(0,pi/2,pi) -> (1,cos,sin) ---
    for (int a = 0; a < 4; ++a) {
        int stride = (a == 0) ? 27 : (a == 1) ? 9 : (a == 2) ? 3 : 1;
        if (tid < 108) {
            int q = tid / 27, line = tid % 27;
            int e0 = line / 9, e1 = (line / 3) % 3, e2 = line % 3;
            int digs[4];
            int ej[3] = { e0, e1, e2 };
            int j = 0;
            for (int pos = 0; pos < 4; ++pos)
                digs[pos] = (pos == a) ? 0 : ej[j++];
            int p0 = digs[0] * 27 + digs[1] * 9 + digs[2] * 3 + digs[3];
            float g0 = G[q][p0], g1 = G[q][p0 + stride], g2 = G[q][p0 + 2 * stride];
            float k1v = 0.5f * (g0 + g2);
            float kcv = 0.5f * (g0 - g2);
            float ksv = g1 - k1v;
            G[q][p0] = k1v;
            G[q][p0 + stride] = kcv;
            G[q][p0 + 2 * stride] = ksv;
        }
        __syncthreads();
    }

    // --- 3. pick sparse monomial coefficients + fold head ---
    if (tid == 0) {
        const int i0[6]  = { 37, 77, 25, 54, 60, 31 };
        const int i1[5]  = { 31, 60, 20, 44, 3 };
        const int i2[6]  = { 10, 52, 75, 56, 78, 1 };
        const int i3[13] = { 30, 17, 47, 67, 5, 42, 61, 18, 9, 51, 76, 38, 26 };
        for (int i = 0; i < 6; ++i)  g_scratch[IK0 + i] = pk2(G[0][i0[i]], G[0][i0[i]]);
        for (int i = 0; i < 5; ++i)  g_scratch[IK1 + i] = pk2(G[1][i1[i]], G[1][i1[i]]);
        for (int i = 0; i < 6; ++i)  g_scratch[IK2 + i] = pk2(G[2][i2[i]], G[2][i2[i]]);
        for (int i = 0; i < 13; ++i) g_scratch[IK3 + i] = pk2(G[3][i3[i]], G[3][i3[i]]);
        for (int q = 0; q < 4; ++q) {
            g_scratch[IW0 + q] = pk2(W[q], W[q]);
            g_scratch[IW1 + q] = pk2(W[4 + q], W[4 + q]);
        }
        float cb0 = b[0] + W[0] * G[0][0] + W[1] * G[1][0] + W[2] * G[2][0] + W[3] * G[3][0];
        float cb1 = b[1] + W[4] * G[0][0] + W[5] * G[1][0] + W[6] * G[2][0] + W[7] * G[3][0];
        g_scratch[IB0] = pk2(cb0, cb0);
        g_scratch[IB1] = pk2(cb1, cb1);
    }
}

__global__ __launch_bounds__(128)
void sim_kernel(const float4* __restrict__ x, float4* __restrict__ out, int Bpair) {
    // Stage constants in shared memory: LDS broadcast (floor 2) replaces the
    // half-rate GPR-dest constant port (floor 8) in the hot path.
    __shared__ u64 sk[NCONST];
    if (threadIdx.x < NCONST) sk[threadIdx.x] = c_flat[threadIdx.x];
    __syncthreads();

    int t = blockIdx.x * blockDim.x + threadIdx.x;
    if (t >= Bpair) return;

    float4 xa = x[2 * t];
    float4 xb = x[2 * t + 1];

    float c0a, s0a, c1a, s1a, c2a, s2a, c3a, s3a;
    float c0b, s0b, c1b, s1b, c2b, s2b, c3b, s3b;
    __sincosf(xa.x, &s0a, &c0a);
    __sincosf(xa.y, &s1a, &c1a);
    __sincosf(xa.z, &s2a, &c2a);
    __sincosf(xa.w, &s3a, &c3a);
    __sincosf(xb.x, &s0b, &c0b);
    __sincosf(xb.y, &s1b, &c1b);
    __sincosf(xb.z, &s2b, &c2b);
    __sincosf(xb.w, &s3b, &c3b);

    u64 C0 = pk2(c0a, c0b), S0 = pk2(s0a, s0b);
    u64 C1 = pk2(c1a, c1b), S1 = pk2(s1a, s1b);
    u64 C2 = pk2(c2a, c2b), S2 = pk2(s2a, s2b);
    u64 C3 = pk2(c3a, c3b), S3 = pk2(s3a, s3b);

    // Pair-grouped monomial walk (32-reg schedule from R14).
    u64 F0 = mul2(sk[IK0 + 3], S0);                    // s0
    u64 F1 = mul2(sk[IK1 + 4], C2);                    // c2
    u64 F2 = mul2(sk[IK2 + 5], C3);                    // c3
    u64 F3 = mul2(sk[IK3 + 7], S1);                    // s1
    F3 = fma2(sk[IK3 + 8], C1, F3);                    // c1

    {   // s0s2 group
        u64 p = mul2(S0, S2);
        F0 = fma2(sk[IK0 + 4], p, F0);                 // s0s2
        F1 = fma2(sk[IK1 + 1], p, F1);                 // s0s2
        F3 = fma2(sk[IK3 + 6], mul2(p, C3), F3);       // s0s2c3
    }
    {   // c0c2 group
        u64 p = mul2(C0, C2);
        F3 = fma2(sk[IK3 + 0], p, F3);                 // c0c2
        u64 m = mul2(p, C3);                           // c0c2c3
        F0 = fma2(sk[IK0 + 5], m, F0);
        F1 = fma2(sk[IK1 + 0], m, F1);
    }
    {   // c2s3 + s0s1 + c2c3 group
        u64 c2s3 = mul2(C2, S3);
        F3 = fma2(sk[IK3 + 4], c2s3, F3);              // c2s3
        u64 s0s1 = mul2(S0, S1);
        F0 = fma2(sk[IK0 + 1], mul2(s0s1, c2s3), F0);  // s0s1c2s3
        F2 = fma2(sk[IK2 + 2], mul2(s0s1, C2), F2);    // s0s1c2
        F2 = fma2(sk[IK2 + 4], mul2(s0s1, S2), F2);    // s0s1s2
        u64 c2c3 = mul2(C2, C3);
        F3 = fma2(sk[IK3 + 10], mul2(s0s1, c2c3), F3); // s0s1c2c3
        F3 = fma2(sk[IK3 + 3], mul2(S0, mul2(C1, c2c3)), F3);  // s0c1c2c3
    }
    {   // s2s3 + c0c1 group
        u64 s2s3 = mul2(S2, S3);
        F3 = fma2(sk[IK3 + 1], mul2(C1, s2s3), F3);    // c1s2s3
        u64 c0c1 = mul2(C0, C1);
        F1 = fma2(sk[IK1 + 3], mul2(c0c1, s2s3), F1);  // c0c1s2s3
        F0 = fma2(sk[IK0 + 0], mul2(c0c1, C3), F0);    // c0c1c3
        F3 = fma2(sk[IK3 + 5], mul2(c0c1, S2), F3);    // c0c1s2
        F3 = fma2(sk[IK3 + 11], mul2(c0c1, S3), F3);   // c0c1s3
    }
    {   // c0s1 group
        u64 p = mul2(C0, S1);
        F3 = fma2(sk[IK3 + 2], mul2(p, S3), F3);       // c0s1s3
        u64 u = mul2(p, S2);                           // c0s1s2
        F3 = fma2(sk[IK3 + 9], u, F3);
        F2 = fma2(sk[IK2 + 1], mul2(u, C3), F2);       // c0s1s2c3
    }
    {   // s1s2 group
        u64 p = mul2(S1, S2);
        F0 = fma2(sk[IK0 + 2], mul2(p, C3), F0);       // s1s2c3
        F3 = fma2(sk[IK3 + 12], mul2(p, S3), F3);      // s1s2s3
    }
    F1 = fma2(sk[IK1 + 2], mul2(S1, S3), F1);          // s1s3
    F2 = fma2(sk[IK2 + 0], mul2(C1, C3), F2);          // c1c3
    F2 = fma2(sk[IK2 + 3], mul2(S0, S3), F2);          // s0s3

    // Head: out_j = b_j' + sum_q W_jq F_q
    u64 o0 = fma2(sk[IW0 + 0], F0, sk[IB0]);
    o0 = fma2(sk[IW0 + 1], F1, o0);
    o0 = fma2(sk[IW0 + 2], F2, o0);
    o0 = fma2(sk[IW0 + 3], F3, o0);
    u64 o1 = fma2(sk[IW1 + 0], F0, sk[IB1]);
    o1 = fma2(sk[IW1 + 1], F1, o1);
    o1 = fma2(sk[IW1 + 2], F2, o1);
    o1 = fma2(sk[IW1 + 3], F3, o1);

    float o0a, o0b, o1a, o1b;
    unpk2(o0, o0a, o0b);
    unpk2(o1, o1a, o1b);

    out[t] = make_float4(o0a, o1a, o0b, o1b);
}

extern "C" void kernel_launch(void* const* d_in, const int* in_sizes, int n_in,
                              void* d_out, int out_size) {
    const float* x       = (const float*)d_in[0];  // (B, 4)
    const float* weights = (const float*)d_in[1];  // (2, 4)
    const float* W       = (const float*)d_in[2];  // (2, 4)
    const float* b       = (const float*)d_in[3];  // (2,)

    int B = in_sizes[0] / 4;
    int Bpair = B / 2;

    setup_kernel<<<1, 128>>>(weights, W, b);

    void* dst = nullptr;
    void* src = nullptr;
    cudaGetSymbolAddress(&dst, c_flat);
    cudaGetSymbolAddress(&src, g_scratch);
    cudaMemcpyAsync(dst, src, sizeof(u64) * NCONST, cudaMemcpyDeviceToDevice, 0);

    sim_kernel<<<(Bpair + 127) / 128, 128>>>((const float4*)x, (float4*)d_out, Bpair);
}

// round 16
// speedup vs baseline: 1.4246x; 1.4246x over previous
#include <cuda_runtime.h>

typedef unsigned long long u64;

// ---------------- packed f32x2 helpers (sm_103a) ----------------
__device__ __forceinline__ u64 pk2(float lo, float hi) {
    u64 r;
    asm("mov.b64 %0, {%1, %2};" : "=l"(r) : "f"(lo), "f"(hi));
    return r;
}
__device__ __forceinline__ void unpk2(u64 v, float& lo, float& hi) {
    asm("mov.b64 {%0, %1}, %2;" : "=f"(lo), "=f"(hi) : "l"(v));
}
__device__ __forceinline__ u64 mul2(u64 a, u64 b) {
    u64 r;
    asm("mul.rn.f32x2 %0, %1, %2;" : "=l"(r) : "l"(a), "l"(b));
    return r;
}
__device__ __forceinline__ u64 fma2(u64 a, u64 b, u64 c) {
    u64 r;
    asm("fma.rn.f32x2 %0, %1, %2, %3;" : "=l"(r) : "l"(a), "l"(b), "l"(c));
    return r;
}

// Heisenberg-picture constants (flat, 40 x u64, both f32x2 lanes duplicated).
struct Consts {
    u64 k0[6];
    u64 k1[5];
    u64 k2[6];
    u64 k3[13];
    u64 w0[4], w1[4];
    u64 b0, b1;
};

__device__ Consts g_scratch;
__constant__ Consts c_consts;

// Fast setup: at grid points x in {0, pi/2, pi} the half-angle trig values are
// the exact constants {1, sqrt(2)/2, 0} — no trig needed for the grid. Only the
// 8 weight half-angles use __sincosf (MUFU fast path; tolerance 1e-3 vs 4e-7).
__global__ void setup_kernel(const float* __restrict__ weights,
                             const float* __restrict__ W,
                             const float* __restrict__ b) {
    __shared__ float G[4][81];
    __shared__ float wc[8], ws[8];
    int tid = threadIdx.x;

    if (tid < 8) {
        float c, s;
        __sincosf(0.5f * weights[tid], &s, &c);
        wc[tid] = c;
        ws[tid] = s;
    }
    __syncthreads();

    // --- 1. simulate circuit features on the 3^4 grid ---
    if (tid < 81) {
        const float R = 0.70710678118654752f;  // sqrt(2)/2
        // half-angle trig at grid digit d: cos in {1, R, 0}, sin in {0, R, 1}
        const float CT[3] = { 1.0f, R, 0.0f };
        const float ST[3] = { 0.0f, R, 1.0f };
        int d[4] = { tid / 27, (tid / 9) % 3, (tid / 3) % 3, tid % 3 };

        float st[16];
#pragma unroll
        for (int s = 0; s < 16; ++s) {
            float v = 1.0f;
#pragma unroll
            for (int i = 0; i < 4; ++i)
                v *= ((s >> (3 - i)) & 1) ? ST[d[i]] : CT[d[i]];
            st[s] = v;
        }
#pragma unroll
        for (int l = 0; l < 2; ++l) {
#pragma unroll
            for (int i = 0; i < 4; ++i) {               // CNOT ring
                int tq = (i + 1) & 3;
                int mc = 1 << (3 - i), mt = 1 << (3 - tq);
#pragma unroll
                for (int s = 0; s < 16; ++s)
                    if ((s & mc) && !(s & mt)) {
                        float tmp = st[s]; st[s] = st[s | mt]; st[s | mt] = tmp;
                    }
            }
#pragma unroll
            for (int i = 0; i < 4; ++i) {               // RY(weights[l][i])
                float c = wc[l * 4 + i], sn = ws[l * 4 + i];
                int m = 1 << (3 - i);
#pragma unroll
                for (int s = 0; s < 16; ++s)
                    if (!(s & m)) {
                        float a0 = st[s], a1 = st[s | m];
                        st[s]     = c * a0 - sn * a1;
                        st[s | m] = sn * a0 + c * a1;
                    }
            }
        }
#pragma unroll
        for (int q = 0; q < 4; ++q) {
            int m = 1 << (3 - q);
            float f = 0.0f;
#pragma unroll
            for (int s = 0; s < 16; ++s) {
                float p = st[s] * st[s];
                f += (s & m) ? -p : p;
            }
            G[q][tid] = f;
        }
    }
    __syncthreads();

    // --- 2. exact per-axis inverse transform: values(0,pi/2,pi) -> (1,cos,sin) ---
    for (int a = 0; a < 4; ++a) {
        int stride = (a == 0) ? 27 : (a == 1) ? 9 : (a == 2) ? 3 : 1;
        if (tid < 108) {
            int q = tid / 27, line = tid % 27;
            int e0 = line / 9, e1 = (line / 3) % 3, e2 = line % 3;
            int digs[4];
            int ej[3] = { e0, e1, e2 };
            int j = 0;
            for (int pos = 0; pos < 4; ++pos)
                digs[pos] = (pos == a) ? 0 : ej[j++];
            int p0 = digs[0] * 27 + digs[1] * 9 + digs[2] * 3 + digs[3];
            float g0 = G[q][p0], g1 = G[q][p0 + stride], g2 = G[q][p0 + 2 * stride];
            float k1v = 0.5f * (g0 + g2);
            float kcv = 0.5f * (g0 - g2);
            float ksv = g1 - k1v;
            G[q][p0] = k1v;
            G[q][p0 + stride] = kcv;
            G[q][p0 + 2 * stride] = ksv;
        }
        __syncthreads();
    }

    // --- 3. pick sparse monomial coefficients + fold head ---
    if (tid == 0) {
        const int i0[6]  = { 37, 77, 25, 54, 60, 31 };
        const int i1[5]  = { 31, 60, 20, 44, 3 };
        const int i2[6]  = { 10, 52, 75, 56, 78, 1 };
        const int i3[13] = { 30, 17, 47, 67, 5, 42, 61, 18, 9, 51, 76, 38, 26 };
        for (int i = 0; i < 6; ++i)  g_scratch.k0[i] = pk2(G[0][i0[i]], G[0][i0[i]]);
        for (int i = 0; i < 5; ++i)  g_scratch.k1[i] = pk2(G[1][i1[i]], G[1][i1[i]]);
        for (int i = 0; i < 6; ++i)  g_scratch.k2[i] = pk2(G[2][i2[i]], G[2][i2[i]]);
        for (int i = 0; i < 13; ++i) g_scratch.k3[i] = pk2(G[3][i3[i]], G[3][i3[i]]);
        for (int q = 0; q < 4; ++q) {
            g_scratch.w0[q] = pk2(W[q], W[q]);
            g_scratch.w1[q] = pk2(W[4 + q], W[4 + q]);
        }
        float cb0 = b[0] + W[0] * G[0][0] + W[1] * G[1][0] + W[2] * G[2][0] + W[3] * G[3][0];
        float cb1 = b[1] + W[4] * G[0][0] + W[5] * G[1][0] + W[6] * G[2][0] + W[7] * G[3][0];
        g_scratch.b0 = pk2(cb0, cb0);
        g_scratch.b1 = pk2(cb1, cb1);
    }
}

__global__ __launch_bounds__(128)
void sim_kernel(const float4* __restrict__ x, float4* __restrict__ out, int Bpair) {
    int t = blockIdx.x * blockDim.x + threadIdx.x;
    if (t >= Bpair) return;

    float4 xa = x[2 * t];
    float4 xb = x[2 * t + 1];

    float c0a, s0a, c1a, s1a, c2a, s2a, c3a, s3a;
    float c0b, s0b, c1b, s1b, c2b, s2b, c3b, s3b;
    __sincosf(xa.x, &s0a, &c0a);
    __sincosf(xa.y, &s1a, &c1a);
    __sincosf(xa.z, &s2a, &c2a);
    __sincosf(xa.w, &s3a, &c3a);
    __sincosf(xb.x, &s0b, &c0b);
    __sincosf(xb.y, &s1b, &c1b);
    __sincosf(xb.z, &s2b, &c2b);
    __sincosf(xb.w, &s3b, &c3b);

    u64 C0 = pk2(c0a, c0b), S0 = pk2(s0a, s0b);
    u64 C1 = pk2(c1a, c1b), S1 = pk2(s1a, s1b);
    u64 C2 = pk2(c2a, c2b), S2 = pk2(s2a, s2b);
    u64 C3 = pk2(c3a, c3b), S3 = pk2(s3a, s3b);

    // Pair-grouped monomial walk (32-reg schedule).
    u64 F0 = mul2(c_consts.k0[3], S0);                 // s0
    u64 F1 = mul2(c_consts.k1[4], C2);                 // c2
    u64 F2 = mul2(c_consts.k2[5], C3);                 // c3
    u64 F3 = mul2(c_consts.k3[7], S1);                 // s1
    F3 = fma2(c_consts.k3[8], C1, F3);                 // c1

    {   // s0s2 group
        u64 p = mul2(S0, S2);
        F0 = fma2(c_consts.k0[4], p, F0);
        F1 = fma2(c_consts.k1[1], p, F1);
        F3 = fma2(c_consts.k3[6], mul2(p, C3), F3);
    }
    {   // c0c2 group
        u64 p = mul2(C0, C2);
        F3 = fma2(c_consts.k3[0], p, F3);
        u64 m = mul2(p, C3);
        F0 = fma2(c_consts.k0[5], m, F0);
        F1 = fma2(c_consts.k1[0], m, F1);
    }
    {   // c2s3 + s0s1 + c2c3 group
        u64 c2s3 = mul2(C2, S3);
        F3 = fma2(c_consts.k3[4], c2s3, F3);
        u64 s0s1 = mul2(S0, S1);
        F0 = fma2(c_consts.k0[1], mul2(s0s1, c2s3), F0);
        F2 = fma2(c_consts.k2[2], mul2(s0s1, C2), F2);
        F2 = fma2(c_consts.k2[4], mul2(s0s1, S2), F2);
        u64 c2c3 = mul2(C2, C3);
        F3 = fma2(c_consts.k3[10], mul2(s0s1, c2c3), F3);
        F3 = fma2(c_consts.k3[3], mul2(S0, mul2(C1, c2c3)), F3);
    }
    {   // s2s3 + c0c1 group
        u64 s2s3 = mul2(S2, S3);
        F3 = fma2(c_consts.k3[1], mul2(C1, s2s3), F3);
        u64 c0c1 = mul2(C0, C1);
        F1 = fma2(c_consts.k1[3], mul2(c0c1, s2s3), F1);
        F0 = fma2(c_consts.k0[0], mul2(c0c1, C3), F0);
        F3 = fma2(c_consts.k3[5], mul2(c0c1, S2), F3);
        F3 = fma2(c_consts.k3[11], mul2(c0c1, S3), F3);
    }
    {   // c0s1 group
        u64 p = mul2(C0, S1);
        F3 = fma2(c_consts.k3[2], mul2(p, S3), F3);
        u64 u = mul2(p, S2);
        F3 = fma2(c_consts.k3[9], u, F3);
        F2 = fma2(c_consts.k2[1], mul2(u, C3), F2);
    }
    {   // s1s2 group
        u64 p = mul2(S1, S2);
        F0 = fma2(c_consts.k0[2], mul2(p, C3), F0);
        F3 = fma2(c_consts.k3[12], mul2(p, S3), F3);
    }
    F1 = fma2(c_consts.k1[2], mul2(S1, S3), F1);
    F2 = fma2(c_consts.k2[0], mul2(C1, C3), F2);
    F2 = fma2(c_consts.k2[3], mul2(S0, S3), F2);

    // Head
    u64 o0 = fma2(c_consts.w0[0], F0, c_consts.b0);
    o0 = fma2(c_consts.w0[1], F1, o0);
    o0 = fma2(c_consts.w0[2], F2, o0);
    o0 = fma2(c_consts.w0[3], F3, o0);
    u64 o1 = fma2(c_consts.w1[0], F0, c_consts.b1);
    o1 = fma2(c_consts.w1[1], F1, o1);
    o1 = fma2(c_consts.w1[2], F2, o1);
    o1 = fma2(c_consts.w1[3], F3, o1);

    float o0a, o0b, o1a, o1b;
    unpk2(o0, o0a, o0b);
    unpk2(o1, o1a, o1b);

    out[t] = make_float4(o0a, o1a, o0b, o1b);
}

extern "C" void kernel_launch(void* const* d_in, const int* in_sizes, int n_in,
                              void* d_out, int out_size) {
    const float* x       = (const float*)d_in[0];  // (B, 4)
    const float* weights = (const float*)d_in[1];  // (2, 4)
    const float* W       = (const float*)d_in[2];  // (2, 4)
    const float* b       = (const float*)d_in[3];  // (2,)

    int B = in_sizes[0] / 4;
    int Bpair = B / 2;

    setup_kernel<<<1, 128>>>(weights, W, b);

    void* dst = nullptr;
    void* src = nullptr;
    cudaGetSymbolAddress(&dst, c_consts);
    cudaGetSymbolAddress(&src, g_scratch);
    cudaMemcpyAsync(dst, src, sizeof(Consts), cudaMemcpyDeviceToDevice, 0);

    sim_kernel<<<(Bpair + 127) / 128, 128>>>((const float4*)x, (float4*)d_out, Bpair);
}